// round 8
// baseline (speedup 1.0000x reference)
#include <cuda_runtime.h>

// out[b,c] = H @ x[b,c] @ H^T for 65536 independent 32x32 fp32 matrices.
// One warp per matrix. f32x2 row-pair accumulators + DCT even/odd butterfly
// fold both contractions to 16 k-steps. R7: stage 2 computes Out^T so it is
// an exact structural clone of stage 1 (4 LDS.128 + 16 fma2 per k). The
// stage-1 accumulators are butterflied across lanes with shfl.bfly(7) and
// stored as a second interleaved (E,O) table; the Htd splat table and the
// per-k stage-2 butterfly (128 fma ops + 2 extra LDS/k) are gone. Final
// store transposes in registers (2 coalesced STG.128 per output row).

#define S_DIM 32
#define EOSTRIDE 68            // 64 data floats + swizzle headroom
#define WARPS_PER_BLOCK 8
#define NTHREADS (WARPS_PER_BLOCK * 32)

typedef unsigned long long u64;

__device__ __forceinline__ void fma2(u64& d, u64 a, u64 b) {
    asm("fma.rn.f32x2 %0, %1, %2, %0;" : "+l"(d) : "l"(a), "l"(b));
}
__device__ __forceinline__ u64 fma2v(u64 a, u64 b, u64 c) {
    u64 d;
    asm("fma.rn.f32x2 %0, %1, %2, %3;" : "=l"(d) : "l"(a), "l"(b), "l"(c));
    return d;
}
__device__ __forceinline__ u64 add2(u64 a, u64 b) {
    u64 d;
    asm("add.rn.f32x2 %0, %1, %2;" : "=l"(d) : "l"(a), "l"(b));
    return d;
}
__device__ __forceinline__ float2 unpack2(u64 u) {
    float2 f;
    asm("mov.b64 {%0, %1}, %2;" : "=f"(f.x), "=f"(f.y) : "l"(u));
    return f;
}

#define NEG1_X2 0xBF800000BF800000ULL   // (-1.0f, -1.0f)

__global__ __launch_bounds__(NTHREADS, 3)
void dct2d_kernel(const float* __restrict__ x,
                  const float* __restrict__ H,
                  float* __restrict__ out,
                  int nMat)
{
    __shared__ __align__(16) float Ht16[16 * S_DIM];   // Ht16[k][i] = H[i][k], k<16
    __shared__ __align__(16) float buf[WARPS_PER_BLOCK][16 * EOSTRIDE];

    const int tid = threadIdx.x;

    // Build Ht16 once per block (shared by BOTH stages now).
    #pragma unroll
    for (int e = tid; e < 16 * S_DIM; e += NTHREADS) {
        int k = e >> 5;          // 0..15
        int i = e & 31;          // 0..31
        Ht16[k * S_DIM + i] = H[i * S_DIM + k];
    }
    __syncthreads();

    const int warp = tid >> 5;
    const int lane = tid & 31;
    const int m = blockIdx.x * WARPS_PER_BLOCK + warp;
    if (m >= nMat) return;

    float* W = buf[warp];
    const float4* __restrict__ src =
        reinterpret_cast<const float4*>(x + (size_t)m * (S_DIM * S_DIM));

    // ---- pass A: coalesced gmem read + butterfly + swizzled EO store ----
    {
        const int o = lane >> 3;
        const int g = lane & 7;
        const int eo_off = g * 8 + ((g >> 2) << 2);
        #pragma unroll
        for (int q = 0; q < 4; q++) {
            int ra = 4 * q + o;
            int rb = 31 - ra;
            float4 a = src[ra * 8 + g];
            float4 b = src[rb * 8 + g];
            float* dstp = &W[ra * EOSTRIDE + eo_off];
            *reinterpret_cast<float4*>(dstp) =
                make_float4(a.x + b.x, a.x - b.x, a.y + b.y, a.y - b.y);
            *reinterpret_cast<float4*>(dstp + 4) =
                make_float4(a.z + b.z, a.z - b.z, a.w + b.w, a.w - b.w);
        }
    }
    __syncwarp();

    const int ti = lane >> 3;
    const int tj = lane & 7;
    const int eo_rd = tj * 8 + ((tj >> 2) << 2);

    // acc[p][c]: stage 1 packs (T[i0+2p][j], T[i0+2p+1][j]), i0=ti*8, j=tj*4+c
    u64 acc[4][4];
    #pragma unroll
    for (int p = 0; p < 4; p++)
        #pragma unroll
        for (int c = 0; c < 4; c++) acc[p][c] = 0ull;

    // ---- stage 1: T[i][j] = sum_{k<16} H[i][k] * (i even ? E : O)[k][j] ----
    #pragma unroll 8
    for (int k = 0; k < 16; k++) {
        ulonglong2 aA = *reinterpret_cast<const ulonglong2*>(&Ht16[k * S_DIM + ti * 8]);
        ulonglong2 aB = *reinterpret_cast<const ulonglong2*>(&Ht16[k * S_DIM + ti * 8 + 4]);
        u64 a[4] = {aA.x, aA.y, aB.x, aB.y};

        ulonglong2 b0 = *reinterpret_cast<const ulonglong2*>(&W[k * EOSTRIDE + eo_rd]);
        ulonglong2 b1 = *reinterpret_cast<const ulonglong2*>(&W[k * EOSTRIDE + eo_rd + 4]);
        u64 b[4] = {b0.x, b0.y, b1.x, b1.y};

        #pragma unroll
        for (int p = 0; p < 4; p++)
            #pragma unroll
            for (int c = 0; c < 4; c++)
                fma2(acc[p][c], a[p], b[c]);
    }
    __syncwarp();

    // ---- cross-lane butterfly: build EO2[j][i] = (T[i][j]±T[i][31-j]) ----
    // Column partner 31-j lives in lane^7 (tj <-> 7-tj, c <-> 3-c). Only
    // acc[p][2],acc[p][3] need exchanging; each lane emits rows for c=0,1.
    {
        u64 r2[4], r3[4];
        #pragma unroll
        for (int p = 0; p < 4; p++) {
            r2[p] = __shfl_xor_sync(0xffffffffu, acc[p][2], 7);
            r3[p] = __shfl_xor_sync(0xffffffffu, acc[p][3], 7);
        }
        const bool low = (tj < 4);
        #pragma unroll
        for (int c = 0; c < 2; c++) {
            int r = low ? (4 * tj + c) : (31 - 4 * tj - c);   // row j < 16
            #pragma unroll
            for (int p = 0; p < 4; p++) {
                u64 part = (c == 0) ? r3[p] : r2[p];          // partner acc[p][3-c]
                u64 own  = acc[p][c];
                u64 xE = add2(own, part);                     // E2[r][i-pair]
                u64 xO = low ? fma2v(part, NEG1_X2, own)      // own - part
                             : fma2v(own,  NEG1_X2, part);    // part - own
                float2 e  = unpack2(xE);
                float2 oo = unpack2(xO);
                int f   = 16 * ti + 4 * p;                    // float index in row
                int off = f + ((f >> 5) << 2);                // same swizzle family
                *reinterpret_cast<float4*>(&W[r * EOSTRIDE + off]) =
                    make_float4(e.x, oo.x, e.y, oo.y);        // interleaved (E,O)
            }
        }
    }
    __syncwarp();

    #pragma unroll
    for (int p = 0; p < 4; p++)
        #pragma unroll
        for (int c = 0; c < 4; c++) acc[p][c] = 0ull;

    // ---- stage 2 (clone of stage 1): Out^T[l][i] = sum_{k<16} H[l][k] *
    //      (l even ? E2 : O2)[k][i]; acc packs (l even, l odd) pairs. ----
    #pragma unroll 8
    for (int k = 0; k < 16; k++) {
        ulonglong2 aA = *reinterpret_cast<const ulonglong2*>(&Ht16[k * S_DIM + ti * 8]);
        ulonglong2 aB = *reinterpret_cast<const ulonglong2*>(&Ht16[k * S_DIM + ti * 8 + 4]);
        u64 a[4] = {aA.x, aA.y, aB.x, aB.y};

        ulonglong2 b0 = *reinterpret_cast<const ulonglong2*>(&W[k * EOSTRIDE + eo_rd]);
        ulonglong2 b1 = *reinterpret_cast<const ulonglong2*>(&W[k * EOSTRIDE + eo_rd + 4]);
        u64 b[4] = {b0.x, b0.y, b1.x, b1.y};

        #pragma unroll
        for (int p = 0; p < 4; p++)
            #pragma unroll
            for (int c = 0; c < 4; c++)
                fma2(acc[p][c], a[p], b[c]);
    }

    // ---- store: acc[p][c] = (Out[i][l0+2p], Out[i][l0+2p+1]),
    //      i = tj*4+c, l0 = ti*8 -> 2 coalesced STG.128 per row i ----
    float* __restrict__ dst = out + (size_t)m * (S_DIM * S_DIM);
    #pragma unroll
    for (int c = 0; c < 4; c++) {
        int i = tj * 4 + c;
        float2 a0 = unpack2(acc[0][c]), a1 = unpack2(acc[1][c]);
        float2 a2 = unpack2(acc[2][c]), a3 = unpack2(acc[3][c]);
        *reinterpret_cast<float4*>(&dst[i * S_DIM + ti * 8]) =
            make_float4(a0.x, a0.y, a1.x, a1.y);
        *reinterpret_cast<float4*>(&dst[i * S_DIM + ti * 8 + 4]) =
            make_float4(a2.x, a2.y, a3.x, a3.y);
    }
}

extern "C" void kernel_launch(void* const* d_in, const int* in_sizes, int n_in,
                              void* d_out, int out_size)
{
    const float* x = (const float*)d_in[0];   // [B, C, 32, 32] fp32
    const float* H = (const float*)d_in[1];   // [32, 32] fp32
    float* out = (float*)d_out;

    int nMat = in_sizes[0] / (S_DIM * S_DIM); // 65536
    int blocks = (nMat + WARPS_PER_BLOCK - 1) / WARPS_PER_BLOCK;

    dct2d_kernel<<<blocks, NTHREADS>>>(x, H, out, nMat);
}

// round 9
// speedup vs baseline: 1.0181x; 1.0181x over previous
#include <cuda_runtime.h>

// out[b,c] = H @ x[b,c] @ H^T for 65536 independent 32x32 fp32 matrices.
// One warp per matrix. f32x2 row-pair accumulators + DCT even/odd butterfly
// fold both contractions to 16 k-steps; stage 2 computes Out^T so it is an
// exact clone of stage 1 (2 broadcast a-LDS + 2 data-LDS + 16 fma2 per k).
// R8: the inter-stage butterfly is IN-LANE (columns {2tj,2tj+1,30-2tj,31-2tj}
// per lane pair j with 31-j inside the lane) -> no shfl, no latency chain.
// All smem access patterns verified conflict-free (EO2 rows swizzled +4*(r>>3)).

#define S_DIM 32
#define EOSTRIDE 68            // 64 data floats + 4 headroom (swizzle shift)
#define WARPS_PER_BLOCK 8
#define NTHREADS (WARPS_PER_BLOCK * 32)

typedef unsigned long long u64;

__device__ __forceinline__ void fma2(u64& d, u64 a, u64 b) {
    asm("fma.rn.f32x2 %0, %1, %2, %0;" : "+l"(d) : "l"(a), "l"(b));
}
__device__ __forceinline__ u64 fma2v(u64 a, u64 b, u64 c) {
    u64 d;
    asm("fma.rn.f32x2 %0, %1, %2, %3;" : "=l"(d) : "l"(a), "l"(b), "l"(c));
    return d;
}
__device__ __forceinline__ u64 add2(u64 a, u64 b) {
    u64 d;
    asm("add.rn.f32x2 %0, %1, %2;" : "=l"(d) : "l"(a), "l"(b));
    return d;
}
__device__ __forceinline__ float2 unpack2(u64 u) {
    float2 f;
    asm("mov.b64 {%0, %1}, %2;" : "=f"(f.x), "=f"(f.y) : "l"(u));
    return f;
}

#define NEG1_X2 0xBF800000BF800000ULL   // (-1.0f, -1.0f)

__global__ __launch_bounds__(NTHREADS, 3)
void dct2d_kernel(const float* __restrict__ x,
                  const float* __restrict__ H,
                  float* __restrict__ out,
                  int nMat)
{
    __shared__ __align__(16) float Ht16[16 * S_DIM];   // Ht16[k][i] = H[i][k], k<16
    __shared__ __align__(16) float buf[WARPS_PER_BLOCK][16 * EOSTRIDE];

    const int tid = threadIdx.x;

    // Build Ht16 once per block (serves both stages).
    #pragma unroll
    for (int e = tid; e < 16 * S_DIM; e += NTHREADS) {
        int k = e >> 5;
        int i = e & 31;
        Ht16[k * S_DIM + i] = H[i * S_DIM + k];
    }
    __syncthreads();

    const int warp = tid >> 5;
    const int lane = tid & 31;
    const int m = blockIdx.x * WARPS_PER_BLOCK + warp;
    if (m >= nMat) return;

    float* W = buf[warp];
    const float4* __restrict__ src =
        reinterpret_cast<const float4*>(x + (size_t)m * (S_DIM * S_DIM));

    // ---- pass A: coalesced gmem read + row butterfly + interleaved EO store
    //      EO[k]: floats (E[k][0],O[k][0],E[k][1],O[k][1],...) col j at 2j.
    //      Store pattern verified uniform across banks (no swizzle needed).
    {
        const int o = lane >> 3;       // row-within-quad
        const int g = lane & 7;        // 16B column group (cols 4g..4g+3)
        #pragma unroll
        for (int q = 0; q < 4; q++) {
            int ra = 4 * q + o;        // 0..15
            int rb = 31 - ra;
            float4 a = src[ra * 8 + g];
            float4 b = src[rb * 8 + g];
            float* dstp = &W[ra * EOSTRIDE + g * 8];
            *reinterpret_cast<float4*>(dstp) =
                make_float4(a.x + b.x, a.x - b.x, a.y + b.y, a.y - b.y);
            *reinterpret_cast<float4*>(dstp + 4) =
                make_float4(a.z + b.z, a.z - b.z, a.w + b.w, a.w - b.w);
        }
    }
    __syncwarp();

    const int ti = lane >> 3;   // i-pair block: rows/cols ti*8 .. ti*8+7
    const int tj = lane & 7;
    // lane's 4 columns: {2tj, 2tj+1, 30-2tj, 31-2tj}  (butterfly pairs in-lane)

    u64 acc[4][4];
    #pragma unroll
    for (int p = 0; p < 4; p++)
        #pragma unroll
        for (int c = 0; c < 4; c++) acc[p][c] = 0ull;

    // ---- stage 1: T[i][j] = sum_{k<16} H[i][k] * (i even ? E : O)[k][j] ----
    #pragma unroll 8
    for (int k = 0; k < 16; k++) {
        ulonglong2 aA = *reinterpret_cast<const ulonglong2*>(&Ht16[k * S_DIM + ti * 8]);
        ulonglong2 aB = *reinterpret_cast<const ulonglong2*>(&Ht16[k * S_DIM + ti * 8 + 4]);
        u64 a[4] = {aA.x, aA.y, aB.x, aB.y};

        const float* rowp = &W[k * EOSTRIDE];
        ulonglong2 q0 = *reinterpret_cast<const ulonglong2*>(rowp + 4 * tj);       // cols 2tj,2tj+1
        ulonglong2 q1 = *reinterpret_cast<const ulonglong2*>(rowp + 60 - 4 * tj);  // cols 30-2tj,31-2tj
        u64 b[4] = {q0.x, q0.y, q1.x, q1.y};

        #pragma unroll
        for (int p = 0; p < 4; p++)
            #pragma unroll
            for (int c = 0; c < 4; c++)
                fma2(acc[p][c], a[p], b[c]);
    }
    __syncwarp();

    // ---- in-lane column butterfly -> EO2 table (overwrites W) ----
    // j=2tj pairs with 31-2tj (c0,c3); j=2tj+1 pairs with 30-2tj (c1,c2).
    // EO2 row r at offset r*EOSTRIDE + 4*(r>>3); (E2,O2) interleaved, i at 2i.
    {
        const int rowA = 2 * tj;
        const int rowB = 2 * tj + 1;
        const int swz  = 4 * (rowA >> 3);             // == 4*(rowB>>3)
        float* baseA = &W[rowA * EOSTRIDE + swz + 16 * ti];
        float* baseB = &W[rowB * EOSTRIDE + swz + 16 * ti];
        #pragma unroll
        for (int p = 0; p < 4; p++) {
            u64 E2A = add2(acc[p][0], acc[p][3]);
            u64 O2A = fma2v(acc[p][3], NEG1_X2, acc[p][0]);   // c0 - c3
            u64 E2B = add2(acc[p][1], acc[p][2]);
            u64 O2B = fma2v(acc[p][2], NEG1_X2, acc[p][1]);   // c1 - c2
            float2 ea = unpack2(E2A), oa = unpack2(O2A);
            float2 eb = unpack2(E2B), ob = unpack2(O2B);
            *reinterpret_cast<float4*>(baseA + 4 * p) =
                make_float4(ea.x, oa.x, ea.y, oa.y);
            *reinterpret_cast<float4*>(baseB + 4 * p) =
                make_float4(eb.x, ob.x, eb.y, ob.y);
        }
    }
    __syncwarp();

    #pragma unroll
    for (int p = 0; p < 4; p++)
        #pragma unroll
        for (int c = 0; c < 4; c++) acc[p][c] = 0ull;

    // ---- stage 2 (clone): Out^T[l][i] = sum_{j<16} H[l][j] *
    //      (l even ? E2 : O2)[j][i];  acc packs (l even, l odd) pairs. ----
    #pragma unroll 8
    for (int k = 0; k < 16; k++) {
        ulonglong2 aA = *reinterpret_cast<const ulonglong2*>(&Ht16[k * S_DIM + ti * 8]);
        ulonglong2 aB = *reinterpret_cast<const ulonglong2*>(&Ht16[k * S_DIM + ti * 8 + 4]);
        u64 a[4] = {aA.x, aA.y, aB.x, aB.y};

        const float* rowp = &W[k * EOSTRIDE + 4 * (k >> 3)];
        ulonglong2 q0 = *reinterpret_cast<const ulonglong2*>(rowp + 4 * tj);
        ulonglong2 q1 = *reinterpret_cast<const ulonglong2*>(rowp + 60 - 4 * tj);
        u64 b[4] = {q0.x, q0.y, q1.x, q1.y};

        #pragma unroll
        for (int p = 0; p < 4; p++)
            #pragma unroll
            for (int c = 0; c < 4; c++)
                fma2(acc[p][c], a[p], b[c]);
    }

    // ---- store: acc[p][c] = (Out[i_c][ti*8+2p], Out[i_c][ti*8+2p+1]) ----
    // i_c = {2tj, 2tj+1, 30-2tj, 31-2tj}; 2 STG.128 per row (sector-optimal).
    float* __restrict__ dst = out + (size_t)m * (S_DIM * S_DIM);
    const int icol[4] = {2 * tj, 2 * tj + 1, 30 - 2 * tj, 31 - 2 * tj};
    #pragma unroll
    for (int c = 0; c < 4; c++) {
        float* rowo = &dst[icol[c] * S_DIM + ti * 8];
        float2 p0 = unpack2(acc[0][c]), p1 = unpack2(acc[1][c]);
        float2 p2 = unpack2(acc[2][c]), p3 = unpack2(acc[3][c]);
        *reinterpret_cast<float4*>(rowo) =
            make_float4(p0.x, p0.y, p1.x, p1.y);
        *reinterpret_cast<float4*>(rowo + 4) =
            make_float4(p2.x, p2.y, p3.x, p3.y);
    }
}

extern "C" void kernel_launch(void* const* d_in, const int* in_sizes, int n_in,
                              void* d_out, int out_size)
{
    const float* x = (const float*)d_in[0];   // [B, C, 32, 32] fp32
    const float* H = (const float*)d_in[1];   // [32, 32] fp32
    float* out = (float*)d_out;

    int nMat = in_sizes[0] / (S_DIM * S_DIM); // 65536
    int blocks = (nMat + WARPS_PER_BLOCK - 1) / WARPS_PER_BLOCK;

    dct2d_kernel<<<blocks, NTHREADS>>>(x, H, out, nMat);
}

// round 11
// speedup vs baseline: 1.5140x; 1.4870x over previous
#include <cuda_runtime.h>
#include <cuda_bf16.h>
#include <cstdint>

// out[b,c] = H @ x[b,c] @ H^T for 65536 independent 32x32 fp32 matrices.
// Tensor-core path via baseline mma.sync (HMMA, compilable on plain sm_103 —
// tcgen05 is NOT available in this toolchain target). bf16 hi/lo split with
// 3 cross terms + fp32 accumulation: rel err ~1e-5.
// One block = 4 matrices, one warp = one matrix (warp-local after staging):
//   stage 1: U = X @ H^T   (A=X frags, B=H-row frags, both plain LDS.32)
//   handoff: split U -> bf16 h/l, store U^T into the reused X region (syncwarp)
//   stage 2: Out = H @ U   (A=H frags, B=U^T frags), coalesced float2 stores.
// All smem rows padded to 40 bf16 (80B = 20 banks) -> every fragment
// load/store pattern is bank-conflict-free.

#define NTHREADS 128
#define XSTR 40                  // bf16 elements per smem row (32 + 8 pad)

__device__ __forceinline__ void split1(float v, unsigned short& h, unsigned short& l) {
    __nv_bfloat16 hb = __float2bfloat16_rn(v);
    float r = v - __bfloat162float(hb);
    h = __bfloat16_as_ushort(hb);
    l = __bfloat16_as_ushort(__float2bfloat16_rn(r));
}

__device__ __forceinline__ uint32_t lds32(const unsigned short* p) {
    return *reinterpret_cast<const uint32_t*>(p);
}

__device__ __forceinline__ void mma16816(float* d, const uint32_t* a,
                                         uint32_t b0, uint32_t b1) {
    asm volatile(
        "mma.sync.aligned.m16n8k16.row.col.f32.bf16.bf16.f32 "
        "{%0,%1,%2,%3}, {%4,%5,%6,%7}, {%8,%9}, {%0,%1,%2,%3};"
        : "+f"(d[0]), "+f"(d[1]), "+f"(d[2]), "+f"(d[3])
        : "r"(a[0]), "r"(a[1]), "r"(a[2]), "r"(a[3]), "r"(b0), "r"(b1));
}

__global__ __launch_bounds__(NTHREADS, 4)
void dct2d_mma_kernel(const float* __restrict__ x,
                      const float* __restrict__ H,
                      float* __restrict__ out,
                      int nMat)
{
    __shared__ __align__(16) unsigned short Xh[128 * XSTR];  // X stack hi; reused as U^T hi
    __shared__ __align__(16) unsigned short Xl[128 * XSTR];  // X stack lo; reused as U^T lo
    __shared__ __align__(16) unsigned short Hh[32 * XSTR];   // H hi (row-major)
    __shared__ __align__(16) unsigned short Hl[32 * XSTR];   // H lo

    const int tid  = threadIdx.x;
    const int w    = tid >> 5;
    const int lane = tid & 31;
    const int g    = lane >> 2;   // mma groupID 0..7
    const int t    = lane & 3;    // mma thread-in-group 0..3

    // ---- stage H: split to bf16 hi/lo ----
    #pragma unroll
    for (int e = tid; e < 1024; e += NTHREADS) {
        int r = e >> 5, c = e & 31;
        unsigned short hh, hl;
        split1(H[e], hh, hl);
        Hh[r * XSTR + c] = hh;
        Hl[r * XSTR + c] = hl;
    }

    // ---- stage X: 4 matrices (4096 floats), coalesced, split hi/lo ----
    {
        const float4* src = reinterpret_cast<const float4*>(x)
                          + (size_t)blockIdx.x * 1024;
        #pragma unroll
        for (int q = 0; q < 8; q++) {
            int f = tid + NTHREADS * q;           // float4 index 0..1023
            float4 v = src[f];
            int row = f >> 3, c4 = f & 7;
            unsigned short h0,l0,h1,l1,h2,l2,h3,l3;
            split1(v.x, h0, l0); split1(v.y, h1, l1);
            split1(v.z, h2, l2); split1(v.w, h3, l3);
            uint2 hv = make_uint2((uint32_t)h0 | ((uint32_t)h1 << 16),
                                  (uint32_t)h2 | ((uint32_t)h3 << 16));
            uint2 lv = make_uint2((uint32_t)l0 | ((uint32_t)l1 << 16),
                                  (uint32_t)l2 | ((uint32_t)l3 << 16));
            *reinterpret_cast<uint2*>(&Xh[row * XSTR + c4 * 4]) = hv;
            *reinterpret_cast<uint2*>(&Xl[row * XSTR + c4 * 4]) = lv;
        }
    }
    __syncthreads();

    // ================= stage 1: U = X_w @ H^T =================
    // A frags from X_w (row-major), B frags from H rows ([n][k], k-contig).
    const unsigned short* Xwh = &Xh[w * 32 * XSTR];
    const unsigned short* Xwl = &Xl[w * 32 * XSTR];

    uint32_t Ah[2][2][4], Al[2][2][4];
    #pragma unroll
    for (int mi = 0; mi < 2; mi++)
        #pragma unroll
        for (int ki = 0; ki < 2; ki++) {
            int r0 = 16 * mi + g;
            int c0 = 16 * ki + 2 * t;
            Ah[mi][ki][0] = lds32(Xwh + r0 * XSTR + c0);
            Ah[mi][ki][1] = lds32(Xwh + (r0 + 8) * XSTR + c0);
            Ah[mi][ki][2] = lds32(Xwh + r0 * XSTR + c0 + 8);
            Ah[mi][ki][3] = lds32(Xwh + (r0 + 8) * XSTR + c0 + 8);
            Al[mi][ki][0] = lds32(Xwl + r0 * XSTR + c0);
            Al[mi][ki][1] = lds32(Xwl + (r0 + 8) * XSTR + c0);
            Al[mi][ki][2] = lds32(Xwl + r0 * XSTR + c0 + 8);
            Al[mi][ki][3] = lds32(Xwl + (r0 + 8) * XSTR + c0 + 8);
        }

    float acc[2][4][4];
    #pragma unroll
    for (int mi = 0; mi < 2; mi++)
        #pragma unroll
        for (int ni = 0; ni < 4; ni++)
            #pragma unroll
            for (int r = 0; r < 4; r++) acc[mi][ni][r] = 0.0f;

    #pragma unroll
    for (int ni = 0; ni < 4; ni++)
        #pragma unroll
        for (int ki = 0; ki < 2; ki++) {
            int br = (8 * ni + g) * XSTR + 16 * ki + 2 * t;
            uint32_t bh0 = lds32(Hh + br), bh1 = lds32(Hh + br + 8);
            uint32_t bl0 = lds32(Hl + br), bl1 = lds32(Hl + br + 8);
            #pragma unroll
            for (int mi = 0; mi < 2; mi++) {
                mma16816(acc[mi][ni], Ah[mi][ki], bh0, bh1);
                mma16816(acc[mi][ni], Ah[mi][ki], bl0, bl1);
                mma16816(acc[mi][ni], Al[mi][ki], bh0, bh1);
            }
        }
    __syncwarp();

    // ---- handoff: U^T (split) into the warp's own X region ----
    // c-reg (mi,ni): c0=U[16mi+g][8ni+2t] c1=col+1 c2=row+8 c3=both(+8,+1)
    // U^T[n][m]: store at row n = 8ni+2t(+1), col m = 16mi+g(+8).
    unsigned short* Uth = &Xh[w * 32 * XSTR];
    unsigned short* Utl = &Xl[w * 32 * XSTR];
    #pragma unroll
    for (int mi = 0; mi < 2; mi++)
        #pragma unroll
        for (int ni = 0; ni < 4; ni++) {
            int rn = 8 * ni + 2 * t;
            int cm = 16 * mi + g;
            unsigned short hh, hl;
            split1(acc[mi][ni][0], hh, hl);
            Uth[rn * XSTR + cm] = hh;          Utl[rn * XSTR + cm] = hl;
            split1(acc[mi][ni][1], hh, hl);
            Uth[(rn + 1) * XSTR + cm] = hh;    Utl[(rn + 1) * XSTR + cm] = hl;
            split1(acc[mi][ni][2], hh, hl);
            Uth[rn * XSTR + cm + 8] = hh;      Utl[rn * XSTR + cm + 8] = hl;
            split1(acc[mi][ni][3], hh, hl);
            Uth[(rn + 1) * XSTR + cm + 8] = hh; Utl[(rn + 1) * XSTR + cm + 8] = hl;
        }
    __syncwarp();

    // ================= stage 2: Out_w = H @ U_w =================
    // A frags from H rows ([l][j]), B frags from U^T ([n][j], j-contig).
    uint32_t Ha[2][2][4], Hal[2][2][4];
    #pragma unroll
    for (int mi = 0; mi < 2; mi++)
        #pragma unroll
        for (int ki = 0; ki < 2; ki++) {
            int r0 = 16 * mi + g;
            int c0 = 16 * ki + 2 * t;
            Ha[mi][ki][0]  = lds32(Hh + r0 * XSTR + c0);
            Ha[mi][ki][1]  = lds32(Hh + (r0 + 8) * XSTR + c0);
            Ha[mi][ki][2]  = lds32(Hh + r0 * XSTR + c0 + 8);
            Ha[mi][ki][3]  = lds32(Hh + (r0 + 8) * XSTR + c0 + 8);
            Hal[mi][ki][0] = lds32(Hl + r0 * XSTR + c0);
            Hal[mi][ki][1] = lds32(Hl + (r0 + 8) * XSTR + c0);
            Hal[mi][ki][2] = lds32(Hl + r0 * XSTR + c0 + 8);
            Hal[mi][ki][3] = lds32(Hl + (r0 + 8) * XSTR + c0 + 8);
        }

    float acc2[2][4][4];
    #pragma unroll
    for (int mi = 0; mi < 2; mi++)
        #pragma unroll
        for (int ni = 0; ni < 4; ni++)
            #pragma unroll
            for (int r = 0; r < 4; r++) acc2[mi][ni][r] = 0.0f;

    #pragma unroll
    for (int ni = 0; ni < 4; ni++)
        #pragma unroll
        for (int ki = 0; ki < 2; ki++) {
            int br = (8 * ni + g) * XSTR + 16 * ki + 2 * t;
            uint32_t bh0 = lds32(Uth + br), bh1 = lds32(Uth + br + 8);
            uint32_t bl0 = lds32(Utl + br), bl1 = lds32(Utl + br + 8);
            #pragma unroll
            for (int mi = 0; mi < 2; mi++) {
                mma16816(acc2[mi][ni], Ha[mi][ki],  bh0, bh1);
                mma16816(acc2[mi][ni], Ha[mi][ki],  bl0, bl1);
                mma16816(acc2[mi][ni], Hal[mi][ki], bh0, bh1);
            }
        }

    // ---- store Out_w: c0/c1 are adjacent cols -> coalesced float2 ----
    float* __restrict__ dst = out + ((size_t)blockIdx.x * 4 + w) * 1024;
    #pragma unroll
    for (int mi = 0; mi < 2; mi++)
        #pragma unroll
        for (int ni = 0; ni < 4; ni++) {
            int l0 = 16 * mi + g;
            int n0 = 8 * ni + 2 * t;
            *reinterpret_cast<float2*>(&dst[l0 * 32 + n0]) =
                make_float2(acc2[mi][ni][0], acc2[mi][ni][1]);
            *reinterpret_cast<float2*>(&dst[(l0 + 8) * 32 + n0]) =
                make_float2(acc2[mi][ni][2], acc2[mi][ni][3]);
        }
}

extern "C" void kernel_launch(void* const* d_in, const int* in_sizes, int n_in,
                              void* d_out, int out_size)
{
    const float* x = (const float*)d_in[0];   // [B, C, 32, 32] fp32
    const float* H = (const float*)d_in[1];   // [32, 32] fp32
    float* out = (float*)d_out;

    int nMat = in_sizes[0] / 1024;            // 65536 (divisible by 4)
    int blocks = nMat / 4;

    dct2d_mma_kernel<<<blocks, NTHREADS>>>(x, H, out, nMat);
}

// round 12
// speedup vs baseline: 1.7358x; 1.1465x over previous
#include <cuda_runtime.h>
#include <cuda_bf16.h>
#include <cstdint>

// out[b,c] = H @ x[b,c] @ H^T for 65536 independent 32x32 fp32 matrices.
// mma.sync bf16 path (plain sm_103; tcgen05 unavailable in this toolchain).
// bf16 hi/lo split, 3 cross terms, fp32 accumulation -> rel err ~5e-6.
// R11: nearly all L1 traffic removed.
//  - X fragments loaded DIRECTLY from gmem as float2 (100% sector efficiency)
//    and split to bf16 hi/lo in registers (packed cvt.rn.bf16x2.f32).
//  - stage1->stage2 transpose done IN REGISTERS with movmatrix.m8n8.trans
//    (acc pair packed to bf16x2 is exactly the m8n8 source fragment).
//  - H fragments loaded once from a tiny padded smem table and reused as
//    stage-1 B frags AND stage-2 A frags (identical element pattern).

#define NTHREADS 128
#define HSTR 40                  // H smem row pitch in bf16 (32 + 8 pad)

__device__ __forceinline__ uint32_t lds32(const unsigned short* p) {
    return *reinterpret_cast<const uint32_t*>(p);
}

__device__ __forceinline__ uint32_t pack_bf16x2(float hi, float lo) {
    uint32_t r;
    asm("cvt.rn.bf16x2.f32 %0, %1, %2;" : "=r"(r) : "f"(hi), "f"(lo));
    return r;
}

__device__ __forceinline__ float bf16lo_f(uint32_t p) {
    return __bfloat162float(__ushort_as_bfloat16((unsigned short)(p & 0xFFFFu)));
}
__device__ __forceinline__ float bf16hi_f(uint32_t p) {
    return __bfloat162float(__ushort_as_bfloat16((unsigned short)(p >> 16)));
}

// split two f32 (v0=k, v1=k+1) into packed bf16x2 hi + residual lo
__device__ __forceinline__ void split2(float v0, float v1,
                                       uint32_t& h, uint32_t& l) {
    h = pack_bf16x2(v1, v0);
    l = pack_bf16x2(v1 - bf16hi_f(h), v0 - bf16lo_f(h));
}

__device__ __forceinline__ uint32_t movm_t(uint32_t a) {
    uint32_t d;
    asm volatile("movmatrix.sync.aligned.m8n8.trans.b16 %0, %1;"
                 : "=r"(d) : "r"(a));
    return d;
}

__device__ __forceinline__ void mma16816(float* d, const uint32_t* a,
                                         uint32_t b0, uint32_t b1) {
    asm volatile(
        "mma.sync.aligned.m16n8k16.row.col.f32.bf16.bf16.f32 "
        "{%0,%1,%2,%3}, {%4,%5,%6,%7}, {%8,%9}, {%0,%1,%2,%3};"
        : "+f"(d[0]), "+f"(d[1]), "+f"(d[2]), "+f"(d[3])
        : "r"(a[0]), "r"(a[1]), "r"(a[2]), "r"(a[3]), "r"(b0), "r"(b1));
}

__global__ __launch_bounds__(NTHREADS, 4)
void dct2d_mma_kernel(const float* __restrict__ x,
                      const float* __restrict__ H,
                      float* __restrict__ out,
                      int nMat)
{
    __shared__ __align__(16) unsigned short Hh[32 * HSTR];
    __shared__ __align__(16) unsigned short Hl[32 * HSTR];

    const int tid  = threadIdx.x;
    const int w    = tid >> 5;
    const int lane = tid & 31;
    const int g    = lane >> 2;   // mma groupID 0..7
    const int t    = lane & 3;    // thread-in-group 0..3

    // ---- stage H into smem (hi/lo split), tiny one-time cost ----
    #pragma unroll
    for (int e = tid; e < 1024; e += NTHREADS) {
        int r = e >> 5, c = e & 31;
        float v = H[e];
        __nv_bfloat16 hb = __float2bfloat16_rn(v);
        Hh[r * HSTR + c] = __bfloat16_as_ushort(hb);
        Hl[r * HSTR + c] =
            __bfloat16_as_ushort(__float2bfloat16_rn(v - __bfloat162float(hb)));
    }
    __syncthreads();

    // ---- H fragments, loaded ONCE, reused by both stages ----
    // Hf[r][ki][e]: e0 = H[8r+g][16ki+2t,+1], e1 = same +8 cols (packed bf16x2)
    uint32_t Hf[4][2][2], Hfl[4][2][2];
    #pragma unroll
    for (int r = 0; r < 4; r++)
        #pragma unroll
        for (int ki = 0; ki < 2; ki++) {
            int off = (8 * r + g) * HSTR + 16 * ki + 2 * t;
            Hf[r][ki][0]  = lds32(Hh + off);
            Hf[r][ki][1]  = lds32(Hh + off + 8);
            Hfl[r][ki][0] = lds32(Hl + off);
            Hfl[r][ki][1] = lds32(Hl + off + 8);
        }

    // ---- X fragments straight from gmem (8 fully-used sectors per LDG) ----
    const float* __restrict__ Xw =
        x + ((size_t)blockIdx.x * 4 + w) * 1024;
    uint32_t Ah[2][2][4], Al[2][2][4];
    #pragma unroll
    for (int mi = 0; mi < 2; mi++)
        #pragma unroll
        for (int ki = 0; ki < 2; ki++) {
            int r0 = 16 * mi + g;
            int c0 = 16 * ki + 2 * t;
            float2 v0 = *reinterpret_cast<const float2*>(Xw + r0 * 32 + c0);
            float2 v1 = *reinterpret_cast<const float2*>(Xw + (r0 + 8) * 32 + c0);
            float2 v2 = *reinterpret_cast<const float2*>(Xw + r0 * 32 + c0 + 8);
            float2 v3 = *reinterpret_cast<const float2*>(Xw + (r0 + 8) * 32 + c0 + 8);
            split2(v0.x, v0.y, Ah[mi][ki][0], Al[mi][ki][0]);
            split2(v1.x, v1.y, Ah[mi][ki][1], Al[mi][ki][1]);
            split2(v2.x, v2.y, Ah[mi][ki][2], Al[mi][ki][2]);
            split2(v3.x, v3.y, Ah[mi][ki][3], Al[mi][ki][3]);
        }

    // ================= stage 1: U = X @ H^T =================
    float acc[2][4][4];
    #pragma unroll
    for (int mi = 0; mi < 2; mi++)
        #pragma unroll
        for (int ni = 0; ni < 4; ni++)
            #pragma unroll
            for (int r = 0; r < 4; r++) acc[mi][ni][r] = 0.0f;

    #pragma unroll
    for (int ni = 0; ni < 4; ni++)
        #pragma unroll
        for (int ki = 0; ki < 2; ki++) {
            uint32_t bh0 = Hf[ni][ki][0],  bh1 = Hf[ni][ki][1];
            uint32_t bl0 = Hfl[ni][ki][0], bl1 = Hfl[ni][ki][1];
            #pragma unroll
            for (int mi = 0; mi < 2; mi++) {
                mma16816(acc[mi][ni], Ah[mi][ki], bh0, bh1);
                mma16816(acc[mi][ni], Ah[mi][ki], bl0, bl1);
                mma16816(acc[mi][ni], Al[mi][ki], bh0, bh1);
            }
        }

    // ---- handoff: in-register transpose via movmatrix ----
    // acc[mi][ni] (c0,c1) packed = m8n8 row frag of U tile (rows 16mi+0..7 via
    // g, cols 8ni+0..7); movmatrix.trans yields the stage-2 col-major B frag:
    // B2[ni][ki=mi][0] (k=2t..) and from (c2,c3) B2[..][1] (k=8+2t..).
    uint32_t B2h[4][2][2], B2l[4][2][2];
    #pragma unroll
    for (int mi = 0; mi < 2; mi++)
        #pragma unroll
        for (int ni = 0; ni < 4; ni++) {
            uint32_t h01, l01, h23, l23;
            split2(acc[mi][ni][0], acc[mi][ni][1], h01, l01);
            split2(acc[mi][ni][2], acc[mi][ni][3], h23, l23);
            B2h[ni][mi][0] = movm_t(h01);
            B2h[ni][mi][1] = movm_t(h23);
            B2l[ni][mi][0] = movm_t(l01);
            B2l[ni][mi][1] = movm_t(l23);
        }

    // ================= stage 2: Out = H @ U =================
    float acc2[2][4][4];
    #pragma unroll
    for (int mi = 0; mi < 2; mi++)
        #pragma unroll
        for (int ni = 0; ni < 4; ni++)
            #pragma unroll
            for (int r = 0; r < 4; r++) acc2[mi][ni][r] = 0.0f;

    #pragma unroll
    for (int ni = 0; ni < 4; ni++)
        #pragma unroll
        for (int ki = 0; ki < 2; ki++) {
            uint32_t bh0 = B2h[ni][ki][0], bh1 = B2h[ni][ki][1];
            uint32_t bl0 = B2l[ni][ki][0], bl1 = B2l[ni][ki][1];
            #pragma unroll
            for (int mi = 0; mi < 2; mi++) {
                // stage-2 A frag of H assembled from the shared Hf registers
                uint32_t a2h[4] = {Hf[2 * mi][ki][0],  Hf[2 * mi + 1][ki][0],
                                   Hf[2 * mi][ki][1],  Hf[2 * mi + 1][ki][1]};
                uint32_t a2l[4] = {Hfl[2 * mi][ki][0], Hfl[2 * mi + 1][ki][0],
                                   Hfl[2 * mi][ki][1], Hfl[2 * mi + 1][ki][1]};
                mma16816(acc2[mi][ni], a2h, bh0, bh1);
                mma16816(acc2[mi][ni], a2h, bl0, bl1);
                mma16816(acc2[mi][ni], a2l, bh0, bh1);
            }
        }

    // ---- store: c0/c1 adjacent cols -> coalesced float2 (8 sectors/instr) ----
    float* __restrict__ dst = out + ((size_t)blockIdx.x * 4 + w) * 1024;
    #pragma unroll
    for (int mi = 0; mi < 2; mi++)
        #pragma unroll
        for (int ni = 0; ni < 4; ni++) {
            int l0 = 16 * mi + g;
            int n0 = 8 * ni + 2 * t;
            *reinterpret_cast<float2*>(&dst[l0 * 32 + n0]) =
                make_float2(acc2[mi][ni][0], acc2[mi][ni][1]);
            *reinterpret_cast<float2*>(&dst[(l0 + 8) * 32 + n0]) =
                make_float2(acc2[mi][ni][2], acc2[mi][ni][3]);
        }
}

extern "C" void kernel_launch(void* const* d_in, const int* in_sizes, int n_in,
                              void* d_out, int out_size)
{
    const float* x = (const float*)d_in[0];   // [B, C, 32, 32] fp32
    const float* H = (const float*)d_in[1];   // [32, 32] fp32
    float* out = (float*)d_out;

    int nMat = in_sizes[0] / 1024;            // 65536 (divisible by 4)
    int blocks = nMat / 4;

    dct2d_mma_kernel<<<blocks, NTHREADS>>>(x, H, out, nMat);
}